// round 5
// baseline (speedup 1.0000x reference)
#include <cuda_runtime.h>
#include <cuda_bf16.h>
#include <cstdint>

// DistMult edge scoring:
//   out[e] = sigmoid( sum_d h[src[e]][d] * W[rel[e]][d] * h[dst[e]][d] )
// E = 1,500,000, D = 128, N = 100,000, R = 6. Indices int32.
//
// R4 (86 us): L1 port 85%, L2 74%, occ 73% (6 blocks/SM @ 38 regs).
// Port-byte floor is ~68-75 us (1536 B/edge through the 128 B/cyc L1/shared
// port); remaining gap is stall slack. R5: squeeze occupancy to 7 blocks/SM
// (__launch_bounds__(256,7), regs<=36) so more resident warps keep the port
// fed. Data path unchanged: 4 edges/warp, 8 lanes/edge, batched LDG.128
// gathers, W in smem, index prefetch one quad ahead.

#define D        128
#define N_RELS   6
#define TPB      256                 // 8 warps per block
#define BLK_PER_SM 7
#define NBLK     (148 * BLK_PER_SM)  // 1036 persistent blocks

__global__ __launch_bounds__(TPB, BLK_PER_SM) void distmult_kernel(
    const float* __restrict__ h,
    const float* __restrict__ W,
    const int* __restrict__ src,
    const int* __restrict__ dst,
    const int* __restrict__ rel,
    float* __restrict__ out,
    int E)
{
    __shared__ float sW[N_RELS * D];   // 3 KB, staged once per block

    for (int i = threadIdx.x; i < N_RELS * D; i += TPB)
        sW[i] = W[i];
    __syncthreads();

    const int lane = threadIdx.x & 31;
    const int sub  = lane >> 3;        // 8-lane group: which of 4 edges
    const int sl   = lane & 7;         // lane within group: dim chunk

    const int n_warps = NBLK * (TPB / 32);
    const int gw      = blockIdx.x * (TPB / 32) + (threadIdx.x >> 5);
    const int Q       = E >> 2;        // edge quads (E % 4 == 0)

    int q = gw;
    int s = 0, d = 0, r = 0;
    if (q < Q) {
        const int e = q * 4 + sub;
        s = __ldcs(&src[e]);           // one 16B broadcast segment per warp
        d = __ldcs(&dst[e]);
        r = __ldcs(&rel[e]);
    }

    while (q < Q) {
        const int e  = q * 4 + sub;
        const int qn = q + n_warps;

        const float4* __restrict__ up = (const float4*)(h + (size_t)s * D);
        const float4* __restrict__ vp = (const float4*)(h + (size_t)d * D);
        const float4* __restrict__ wp = (const float4*)(sW + r * D);

        // Batch all 8 gather loads (max MLP, fully coalesced 128B lines).
        float4 u0 = __ldg(up + sl);
        float4 u1 = __ldg(up + sl + 8);
        float4 u2 = __ldg(up + sl + 16);
        float4 u3 = __ldg(up + sl + 24);
        float4 v0 = __ldg(vp + sl);
        float4 v1 = __ldg(vp + sl + 8);
        float4 v2 = __ldg(vp + sl + 16);
        float4 v3 = __ldg(vp + sl + 24);

        // Prefetch next quad's indices while gathers are in flight.
        int sn = 0, dn = 0, rn = 0;
        if (qn < Q) {
            const int en = qn * 4 + sub;
            sn = __ldcs(&src[en]);
            dn = __ldcs(&dst[en]);
            rn = __ldcs(&rel[en]);
        }

        // W consumed chunk-by-chunk from smem (conflict-free 128B phases).
        float acc;
        {
            float4 w = wp[sl];
            acc  = u0.x * w.x * v0.x + u0.y * w.y * v0.y
                 + u0.z * w.z * v0.z + u0.w * w.w * v0.w;
        }
        {
            float4 w = wp[sl + 8];
            acc += u1.x * w.x * v1.x + u1.y * w.y * v1.y
                 + u1.z * w.z * v1.z + u1.w * w.w * v1.w;
        }
        {
            float4 w = wp[sl + 16];
            acc += u2.x * w.x * v2.x + u2.y * w.y * v2.y
                 + u2.z * w.z * v2.z + u2.w * w.w * v2.w;
        }
        {
            float4 w = wp[sl + 24];
            acc += u3.x * w.x * v3.x + u3.y * w.y * v3.y
                 + u3.z * w.z * v3.z + u3.w * w.w * v3.w;
        }

        // Reduce within the 8-lane group.
        acc += __shfl_xor_sync(0xFFFFFFFFu, acc, 4);
        acc += __shfl_xor_sync(0xFFFFFFFFu, acc, 2);
        acc += __shfl_xor_sync(0xFFFFFFFFu, acc, 1);

        if (sl == 0) {
            float sig = 1.0f / (1.0f + __expf(-acc));
            __stcs(&out[e], sig);      // 4 lanes/warp: 1 coalesced 16B segment
        }

        s = sn; d = dn; r = rn; q = qn;
    }
}

extern "C" void kernel_launch(void* const* d_in, const int* in_sizes, int n_in,
                              void* d_out, int out_size)
{
    const float* h   = (const float*)d_in[0];
    const float* W   = (const float*)d_in[1];
    const int*   src = (const int*)d_in[2];
    const int*   dst = (const int*)d_in[3];
    const int*   rel = (const int*)d_in[4];
    float* out = (float*)d_out;

    const int E = in_sizes[2];

    int quads  = E >> 2;
    int blocks = (quads + (TPB / 32) - 1) / (TPB / 32);
    if (blocks > NBLK) blocks = NBLK;

    distmult_kernel<<<blocks, TPB>>>(h, W, src, dst, rel, out, E);
}